// round 2
// baseline (speedup 1.0000x reference)
#include <cuda_runtime.h>
#include <math.h>

#define BN 32
#define CN 1024
#define QN 128
#define DN 768
#define ODN 3072
#define LDP 132
#define SMEM_FLOATS (QN*LDP + 4224)
#define SMEM_BYTES (SMEM_FLOATS*4)

// ---------------- scratch (__device__ globals; no allocation) ----------------
__device__ float g_A[(size_t)BN*QN*DN];   // wc + query*wqc   (12.6 MB)
__device__ float g_xq[BN*QN];             // query . wq
__device__ float g_m[BN*CN];              // row max of masked sim
__device__ float g_w[BN*CN];              // q2c softmax weights
__device__ float g_q2c[BN*DN];            // q2c vector per batch

__device__ __forceinline__ float finf() { return __int_as_float(0x7f800000); }

// ---------------- kernel 1: A = wc + query*wqc ; xq = query . wq -------------
__global__ void prep_kernel(const float* __restrict__ query,
                            const float* __restrict__ wq,
                            const float* __restrict__ wc,
                            const float* __restrict__ wqc) {
    int row = blockIdx.x;          // b*QN + q
    int t = threadIdx.x;           // 0..191 (768/4)
    float4 q4  = reinterpret_cast<const float4*>(query)[(size_t)row*192 + t];
    float4 wq4 = reinterpret_cast<const float4*>(wq)[t];
    float4 wc4 = reinterpret_cast<const float4*>(wc)[t];
    float4 wqc4= reinterpret_cast<const float4*>(wqc)[t];
    float4 a4;
    a4.x = wc4.x + q4.x*wqc4.x;
    a4.y = wc4.y + q4.y*wqc4.y;
    a4.z = wc4.z + q4.z*wqc4.z;
    a4.w = wc4.w + q4.w*wqc4.w;
    reinterpret_cast<float4*>(g_A)[(size_t)row*192 + t] = a4;
    float dot = q4.x*wq4.x + q4.y*wq4.y + q4.z*wq4.z + q4.w*wq4.w;
    #pragma unroll
    for (int o=16;o;o>>=1) dot += __shfl_xor_sync(0xffffffffu, dot, o);
    __shared__ float red[6];
    if ((t&31)==0) red[t>>5]=dot;
    __syncthreads();
    if (t==0) g_xq[row] = red[0]+red[1]+red[2]+red[3]+red[4]+red[5];
}

// ---------------- kernel 2: main fused sim->softmax->c2q ---------------------
// grid (8, 32): blockIdx.x = c-tile (128 rows), blockIdx.y = b. 256 threads.
__global__ __launch_bounds__(256, 2)
void main_kernel(const float* __restrict__ ctx,
                 const int* __restrict__ cmask,
                 const float* __restrict__ query,
                 const int* __restrict__ qmask,
                 float* __restrict__ out) {
    extern __shared__ float smf[];
    float* sP = smf;                 // [128 q][LDP] normalized probs (q-major)
    float* sT = smf + QN*LDP;        // 4224 floats: GEMM1 dbl-buf / GEMM2 q tiles

    const int b = blockIdx.y;
    const int cbase = blockIdx.x << 7;
    const int tid = threadIdx.x;
    const int tx = tid & 15, ty = tid >> 4;
    const int lr = tid >> 1;          // 0..127 row for tile loads
    const int lk = (tid & 1) << 2;    // 0 or 4

    const float* ctxB = ctx + ((size_t)(b*CN + cbase))*DN;
    const float* Ab   = g_A + (size_t)b*QN*DN;

    int rI[8], cJ[8];
    #pragma unroll
    for (int h=0;h<2;h++)
      #pragma unroll
      for (int i=0;i<4;i++) {
        rI[h*4+i] = h*64 + ty*4 + i;
        cJ[h*4+i] = h*64 + tx*4 + i;
      }

    float acc[8][8];
    #pragma unroll
    for (int i=0;i<8;i++)
      #pragma unroll
      for (int j=0;j<8;j++) acc[i][j]=0.f;

    // -------- GEMM1: S[c,q] = ctx_tile . A^T, K=768, BK=8 double-buffered ----
    {
        float4 cg = *reinterpret_cast<const float4*>(ctxB + (size_t)lr*DN + lk);
        float4 ag = *reinterpret_cast<const float4*>(Ab  + (size_t)lr*DN + lk);
        float* sc = sT; float* sa = sT + 1056;
        sc[(lk+0)*LDP+lr]=cg.x; sc[(lk+1)*LDP+lr]=cg.y; sc[(lk+2)*LDP+lr]=cg.z; sc[(lk+3)*LDP+lr]=cg.w;
        sa[(lk+0)*LDP+lr]=ag.x; sa[(lk+1)*LDP+lr]=ag.y; sa[(lk+2)*LDP+lr]=ag.z; sa[(lk+3)*LDP+lr]=ag.w;
    }
    __syncthreads();
    int buf = 0;
    for (int kt=0; kt<96; kt++) {
        float4 ncg, nag;
        if (kt < 95) {
            int ko = (kt+1)*8 + lk;
            ncg = *reinterpret_cast<const float4*>(ctxB + (size_t)lr*DN + ko);
            nag = *reinterpret_cast<const float4*>(Ab  + (size_t)lr*DN + ko);
        }
        const float* sc = sT + buf*2112;
        const float* sa = sc + 1056;
        #pragma unroll
        for (int kk=0; kk<8; kk++) {
            float af[8], bf[8];
            float4 a0 = *reinterpret_cast<const float4*>(sc + kk*LDP + ty*4);
            float4 a1 = *reinterpret_cast<const float4*>(sc + kk*LDP + 64 + ty*4);
            float4 b0 = *reinterpret_cast<const float4*>(sa + kk*LDP + tx*4);
            float4 b1 = *reinterpret_cast<const float4*>(sa + kk*LDP + 64 + tx*4);
            af[0]=a0.x; af[1]=a0.y; af[2]=a0.z; af[3]=a0.w;
            af[4]=a1.x; af[5]=a1.y; af[6]=a1.z; af[7]=a1.w;
            bf[0]=b0.x; bf[1]=b0.y; bf[2]=b0.z; bf[3]=b0.w;
            bf[4]=b1.x; bf[5]=b1.y; bf[6]=b1.z; bf[7]=b1.w;
            #pragma unroll
            for (int i=0;i<8;i++)
              #pragma unroll
              for (int j=0;j<8;j++)
                acc[i][j] = fmaf(af[i], bf[j], acc[i][j]);
        }
        if (kt < 95) {
            float* dc = sT + (buf^1)*2112; float* da = dc + 1056;
            dc[(lk+0)*LDP+lr]=ncg.x; dc[(lk+1)*LDP+lr]=ncg.y; dc[(lk+2)*LDP+lr]=ncg.z; dc[(lk+3)*LDP+lr]=ncg.w;
            da[(lk+0)*LDP+lr]=nag.x; da[(lk+1)*LDP+lr]=nag.y; da[(lk+2)*LDP+lr]=nag.z; da[(lk+3)*LDP+lr]=nag.w;
            __syncthreads();
            buf ^= 1;
        }
    }

    // -------- bias + masks (faithful inf-multiply semantics) -----------------
    float qmf[8], xq8[8];
    #pragma unroll
    for (int j=0;j<8;j++) {
        int q = cJ[j];
        qmf[j] = (qmask[b*QN + q] == 1) ? 1.0f : -finf();
        xq8[j] = g_xq[b*QN + q];
    }
    float cmf[8];
    #pragma unroll
    for (int i=0;i<8;i++)
        cmf[i] = (cmask[b*CN + cbase + rI[i]] == 1) ? 1.0f : -finf();
    #pragma unroll
    for (int i=0;i<8;i++)
      #pragma unroll
      for (int j=0;j<8;j++) {
        float v = (acc[i][j] + xq8[j]) * cmf[i] * qmf[j];
        if (v == finf()) v = -finf();
        acc[i][j] = v;
      }

    // -------- row softmax over q (16 lanes per row share a half-warp) --------
    #pragma unroll
    for (int i=0;i<8;i++) {
        float mx = acc[i][0];
        #pragma unroll
        for (int j=1;j<8;j++) mx = fmaxf(mx, acc[i][j]);
        #pragma unroll
        for (int o=1;o<16;o<<=1) mx = fmaxf(mx, __shfl_xor_sync(0xffffffffu, mx, o));
        if (tx == 0) g_m[b*CN + cbase + rI[i]] = mx;
        float s = 0.f;
        #pragma unroll
        for (int j=0;j<8;j++) { float e = expf(acc[i][j] - mx); acc[i][j] = e; s += e; }
        #pragma unroll
        for (int o=1;o<16;o<<=1) s += __shfl_xor_sync(0xffffffffu, s, o);
        float inv = 1.0f / s;
        #pragma unroll
        for (int j=0;j<8;j++) acc[i][j] *= inv;
    }

    // store P transposed: sP[q][c]
    #pragma unroll
    for (int i=0;i<8;i++)
      #pragma unroll
      for (int j=0;j<8;j++)
        sP[cJ[j]*LDP + rI[i]] = acc[i][j];
    __syncthreads();

    // -------- GEMM2 per 128-d tile: O = P @ query; write parts 1/2/3 ---------
    const float* qB = query + (size_t)b*QN*DN;
    const int lr2 = tid >> 5;          // 0..7
    const int lc4 = (tid & 31) << 2;   // 0..124

    for (int dt=0; dt<6; dt++) {
        const int dbase = dt << 7;
        #pragma unroll
        for (int i=0;i<8;i++)
          #pragma unroll
          for (int j=0;j<8;j++) acc[i][j]=0.f;
        {
            float4 qg = *reinterpret_cast<const float4*>(qB + (size_t)lr2*DN + dbase + lc4);
            *reinterpret_cast<float4*>(sT + lr2*LDP + lc4) = qg;
        }
        __syncthreads();
        int b2 = 0;
        for (int kt=0; kt<16; kt++) {
            float4 nqg;
            if (kt < 15)
                nqg = *reinterpret_cast<const float4*>(qB + (size_t)((kt+1)*8 + lr2)*DN + dbase + lc4);
            const float* sq = sT + b2*1056;
            const float* sp = sP + kt*8*LDP;
            #pragma unroll
            for (int kk=0;kk<8;kk++) {
                float af[8], bf[8];
                float4 a0 = *reinterpret_cast<const float4*>(sp + kk*LDP + ty*4);
                float4 a1 = *reinterpret_cast<const float4*>(sp + kk*LDP + 64 + ty*4);
                float4 b0 = *reinterpret_cast<const float4*>(sq + kk*LDP + tx*4);
                float4 b1 = *reinterpret_cast<const float4*>(sq + kk*LDP + 64 + tx*4);
                af[0]=a0.x; af[1]=a0.y; af[2]=a0.z; af[3]=a0.w;
                af[4]=a1.x; af[5]=a1.y; af[6]=a1.z; af[7]=a1.w;
                bf[0]=b0.x; bf[1]=b0.y; bf[2]=b0.z; bf[3]=b0.w;
                bf[4]=b1.x; bf[5]=b1.y; bf[6]=b1.z; bf[7]=b1.w;
                #pragma unroll
                for (int i=0;i<8;i++)
                  #pragma unroll
                  for (int j=0;j<8;j++)
                    acc[i][j] = fmaf(af[i], bf[j], acc[i][j]);
            }
            if (kt < 15) {
                float* dq = sT + (b2^1)*1056;
                *reinterpret_cast<float4*>(dq + lr2*LDP + lc4) = nqg;
                __syncthreads();
                b2 ^= 1;
            }
        }
        // write out: part1 = ctx, part2 = c2q, part3 = ctx*c2q
        #pragma unroll
        for (int i=0;i<8;i++) {
            const size_t row = (size_t)(b*CN + cbase + rI[i]);
            const float* cp = ctx + row*DN + dbase;
            float* op = out + row*ODN + dbase;
            #pragma unroll
            for (int h=0; h<2; h++) {
                int d0 = h*64 + tx*4;
                float4 cv = *reinterpret_cast<const float4*>(cp + d0);
                float4 ov = make_float4(acc[i][h*4+0], acc[i][h*4+1], acc[i][h*4+2], acc[i][h*4+3]);
                *reinterpret_cast<float4*>(op + d0) = cv;
                *reinterpret_cast<float4*>(op + DN + d0) = ov;
                float4 pv = make_float4(cv.x*ov.x, cv.y*ov.y, cv.z*ov.z, cv.w*ov.w);
                *reinterpret_cast<float4*>(op + 2*DN + d0) = pv;
            }
        }
    }
}

// ---------------- kernel 3: q2c weights = softmax over c of g_m --------------
__global__ void softc_kernel() {
    int b = blockIdx.x, t = threadIdx.x;  // 256 threads
    float v[4]; float mx = -finf();
    #pragma unroll
    for (int i=0;i<4;i++) { v[i] = g_m[b*CN + t + i*256]; mx = fmaxf(mx, v[i]); }
    #pragma unroll
    for (int o=16;o;o>>=1) mx = fmaxf(mx, __shfl_xor_sync(0xffffffffu, mx, o));
    __shared__ float smx[8], ssm[8];
    if ((t&31)==0) smx[t>>5]=mx;
    __syncthreads();
    float bm = smx[0];
    #pragma unroll
    for (int i=1;i<8;i++) bm = fmaxf(bm, smx[i]);
    float s = 0.f;
    #pragma unroll
    for (int i=0;i<4;i++) { float e = expf(v[i]-bm); v[i]=e; s+=e; }
    #pragma unroll
    for (int o=16;o;o>>=1) s += __shfl_xor_sync(0xffffffffu, s, o);
    if ((t&31)==0) ssm[t>>5]=s;
    __syncthreads();
    float tot = ssm[0]+ssm[1]+ssm[2]+ssm[3]+ssm[4]+ssm[5]+ssm[6]+ssm[7];
    float inv = 1.0f / tot;
    #pragma unroll
    for (int i=0;i<4;i++) g_w[b*CN + t + i*256] = v[i]*inv;
}

// ---------------- kernel 4: q2c[b,d] = sum_c w[b,c]*ctx[b,c,d] ---------------
// grid (6, 32), 256 threads: 128 d-cols x 2 c-halves
__global__ void q2c_kernel(const float* __restrict__ ctx) {
    int b = blockIdx.y;
    int dbase = blockIdx.x << 7;
    int t = threadIdx.x;
    int col = t & 127;
    int half = t >> 7;
    const float* cp = ctx + ((size_t)(b*CN) + half*512)*DN + dbase + col;
    const float* wp = g_w + b*CN + half*512;
    float a0=0.f,a1=0.f,a2=0.f,a3=0.f;
    for (int c=0;c<512;c+=4) {
        a0 += wp[c+0]*cp[(size_t)(c+0)*DN];
        a1 += wp[c+1]*cp[(size_t)(c+1)*DN];
        a2 += wp[c+2]*cp[(size_t)(c+2)*DN];
        a3 += wp[c+3]*cp[(size_t)(c+3)*DN];
    }
    float acc = (a0+a1)+(a2+a3);
    __shared__ float sred[128];
    if (half) sred[col] = acc;
    __syncthreads();
    if (!half) g_q2c[(size_t)b*DN + dbase + col] = acc + sred[col];
}

// ---------------- kernel 5: part4 = ctx * q2c (elementwise) ------------------
__global__ void part4_kernel(const float* __restrict__ ctx, float* __restrict__ out) {
    int i4 = blockIdx.x*blockDim.x + threadIdx.x;   // < BN*CN*192
    int bc = i4 / 192;
    int d4 = i4 - bc*192;
    float4 cv = reinterpret_cast<const float4*>(ctx)[(size_t)bc*192 + d4];
    float4 qv = reinterpret_cast<const float4*>(g_q2c)[(bc>>10)*192 + d4];
    float4 r = make_float4(cv.x*qv.x, cv.y*qv.y, cv.z*qv.z, cv.w*qv.w);
    reinterpret_cast<float4*>(out)[(size_t)bc*768 + 576 + d4] = r;
}

// ---------------- launch -----------------------------------------------------
extern "C" void kernel_launch(void* const* d_in, const int* in_sizes, int n_in,
                              void* d_out, int out_size) {
    const float* ctx   = (const float*)d_in[0];
    const int*   cmask = (const int*)d_in[1];
    const float* query = (const float*)d_in[2];
    const int*   qmask = (const int*)d_in[3];
    const float* wq    = (const float*)d_in[4];
    const float* wc    = (const float*)d_in[5];
    const float* wqc   = (const float*)d_in[6];
    float* out = (float*)d_out;

    cudaFuncSetAttribute(main_kernel, cudaFuncAttributeMaxDynamicSharedMemorySize, SMEM_BYTES);

    prep_kernel<<<BN*QN, 192>>>(query, wq, wc, wqc);
    main_kernel<<<dim3(8, BN), 256, SMEM_BYTES>>>(ctx, cmask, query, qmask, out);
    softc_kernel<<<BN, 256>>>();
    q2c_kernel<<<dim3(6, BN), 256>>>(ctx);
    part4_kernel<<<(BN*CN*192)/256, 256>>>(ctx, out);
}

// round 4
// speedup vs baseline: 1.7780x; 1.7780x over previous
#include <cuda_runtime.h>
#include <math.h>
#include <stdint.h>

#define BN 32
#define CN 1024
#define QN 128
#define DN 768
#define ODN 3072

// ---------------- smem layout (float offsets) --------------------------------
#define RA_F    0        // region A: 10240 f (GEMM1 stages / QT chunk / O stage)
#define P_F     10240    // P: 128*132 = 16896 f
#define SXQ_F   27136    // 128 f
#define SQM_F   27264    // 128 f
#define SCM_F   27392    // 128 f
#define SRED_F  27520    // 512 f
#define SMEM_FLOATS 28032
#define SMEM_BYTES (SMEM_FLOATS*4)

// ---------------- scratch ----------------------------------------------------
__device__ float g_A[(size_t)BN*QN*DN];    // wc + query*wqc
__device__ float g_QT[(size_t)BN*DN*QN];   // query transposed [b][d][q]
__device__ float g_xq[BN*QN];
__device__ float g_m[BN*CN];
__device__ float g_w[BN*CN];
__device__ float g_qp[(size_t)BN*8*DN];    // q2c partials
__device__ float g_q2c[BN*DN];

__device__ __forceinline__ float finf() { return __int_as_float(0x7f800000); }

__device__ __forceinline__ uint32_t s2u(const void* p) {
    uint32_t a;
    asm("{ .reg .u64 t; cvta.to.shared.u64 t, %1; cvt.u32.u64 %0, t; }" : "=r"(a) : "l"(p));
    return a;
}
__device__ __forceinline__ void cpa16(uint32_t dst, const void* src) {
    asm volatile("cp.async.cg.shared.global [%0], [%1], 16;" :: "r"(dst), "l"(src));
}
#define CP_COMMIT() asm volatile("cp.async.commit_group;" ::: "memory")
#define CP_WAIT0()  asm volatile("cp.async.wait_group 0;" ::: "memory")
#define CP_WAIT1()  asm volatile("cp.async.wait_group 1;" ::: "memory")

// m16n8k8 tf32 mma, D += A*B (fp32 accum). Raw fp32 bits as tf32 operands.
__device__ __forceinline__ void mma8(float* d, const uint32_t* a, const uint32_t* b) {
    asm volatile("mma.sync.aligned.m16n8k8.row.col.f32.tf32.tf32.f32 "
        "{%0,%1,%2,%3}, {%4,%5,%6,%7}, {%8,%9}, {%0,%1,%2,%3};"
        : "+f"(d[0]), "+f"(d[1]), "+f"(d[2]), "+f"(d[3])
        : "r"(a[0]), "r"(a[1]), "r"(a[2]), "r"(a[3]), "r"(b[0]), "r"(b[1]));
}

// ---------------- kernel 1: A = wc + query*wqc ; xq = query . wq -------------
__global__ void prep_kernel(const float* __restrict__ query,
                            const float* __restrict__ wq,
                            const float* __restrict__ wc,
                            const float* __restrict__ wqc) {
    int row = blockIdx.x;
    int t = threadIdx.x;           // 0..191
    float4 q4  = reinterpret_cast<const float4*>(query)[(size_t)row*192 + t];
    float4 wq4 = reinterpret_cast<const float4*>(wq)[t];
    float4 wc4 = reinterpret_cast<const float4*>(wc)[t];
    float4 wqc4= reinterpret_cast<const float4*>(wqc)[t];
    float4 a4;
    a4.x = wc4.x + q4.x*wqc4.x;
    a4.y = wc4.y + q4.y*wqc4.y;
    a4.z = wc4.z + q4.z*wqc4.z;
    a4.w = wc4.w + q4.w*wqc4.w;
    reinterpret_cast<float4*>(g_A)[(size_t)row*192 + t] = a4;
    float dot = q4.x*wq4.x + q4.y*wq4.y + q4.z*wq4.z + q4.w*wq4.w;
    #pragma unroll
    for (int o=16;o;o>>=1) dot += __shfl_xor_sync(0xffffffffu, dot, o);
    __shared__ float red[6];
    if ((t&31)==0) red[t>>5]=dot;
    __syncthreads();
    if (t==0) g_xq[row] = red[0]+red[1]+red[2]+red[3]+red[4]+red[5];
}

// ---------------- kernel 1b: QT[b][d][q] = query[b][q][d] --------------------
__global__ void qtrans_kernel(const float* __restrict__ query) {
    __shared__ float tile[32][33];
    int b = blockIdx.z, dt = blockIdx.x, qt = blockIdx.y;
    int tx = threadIdx.x, ty = threadIdx.y;   // (32,8)
    const float* qb = query + (size_t)b*QN*DN;
    #pragma unroll
    for (int i=0;i<32;i+=8)
        tile[ty+i][tx] = qb[(size_t)(qt*32+ty+i)*DN + dt*32+tx];
    __syncthreads();
    float* QTb = g_QT + (size_t)b*DN*QN;
    #pragma unroll
    for (int i=0;i<32;i+=8)
        QTb[(size_t)(dt*32+ty+i)*QN + qt*32+tx] = tile[tx][ty+i];
}

// ---------------- kernel 2: main fused mma.sync kernel -----------------------
// grid (8, 32), 256 threads (8 warps in 2x4). smem 112128 B, 2 CTAs/SM.
__device__ __forceinline__ void load_g1(const float* ctxB, const float* AqB,
                                        uint32_t sb, int kt, int stage, int tid) {
    int k0 = kt*16;
    int base = stage*5120;
    #pragma unroll
    for (int p=0;p<2;p++) {
        int idx = tid + p*256;
        int row = idx>>2, seg = idx&3;
        uint32_t off = (uint32_t)(base + row*20 + seg*4)*4;
        cpa16(sb + off,          ctxB + (size_t)row*DN + k0 + seg*4);
        cpa16(sb + off + 10240,  AqB  + (size_t)row*DN + k0 + seg*4);
    }
}

__global__ __launch_bounds__(256, 2)
void main_kernel(const float* __restrict__ ctx,
                 const int* __restrict__ cmask,
                 const int* __restrict__ qmask,
                 float* __restrict__ out) {
    extern __shared__ float smf[];
    const uint32_t sb = s2u(smf);
    const int tid = threadIdx.x;
    const int wid = tid >> 5, lane = tid & 31;
    const int g = lane >> 2, t = lane & 3;
    const int wm = wid >> 2, wn = wid & 3;   // 2 x 4 warp grid
    const int b = blockIdx.y;
    const int cbase = blockIdx.x << 7;
    const float* ctxB = ctx + ((size_t)(b*CN + cbase))*DN;
    const float* AqB  = g_A + (size_t)b*QN*DN;

    if (tid < 128) {
        smf[SXQ_F + tid] = g_xq[b*QN + tid];
        smf[SQM_F + tid] = (qmask[b*QN + tid] == 1) ? 1.0f : -finf();
        smf[SCM_F + tid] = (cmask[b*CN + cbase + tid] == 1) ? 1.0f : -finf();
    }

    float acc[4][4][4];
    #pragma unroll
    for (int mt=0;mt<4;mt++)
      #pragma unroll
      for (int nt=0;nt<4;nt++)
        #pragma unroll
        for (int r=0;r<4;r++) acc[mt][nt][r]=0.f;

    // -------- GEMM1: S[128c,128q] = ctx @ A^T, K=768, chunks of 16 -----------
    load_g1(ctxB, AqB, sb, 0, 0, tid);
    CP_COMMIT();
    for (int kt = 0; kt < 48; kt++) {
        if (kt < 47) { load_g1(ctxB, AqB, sb, kt+1, (kt+1)&1, tid); CP_COMMIT(); CP_WAIT1(); }
        else CP_WAIT0();
        __syncthreads();
        const float* ct = smf + (kt&1)*5120;
        const float* at = ct + 2560;
        #pragma unroll
        for (int k8=0;k8<2;k8++) {
            uint32_t a[4][4], bb[4][2];
            #pragma unroll
            for (int mt=0;mt<4;mt++) {
                int r0 = wm*64 + mt*16 + g;
                a[mt][0] = __float_as_uint(ct[ r0   *20 + k8*8 + t]);
                a[mt][1] = __float_as_uint(ct[(r0+8)*20 + k8*8 + t]);
                a[mt][2] = __float_as_uint(ct[ r0   *20 + k8*8 + t+4]);
                a[mt][3] = __float_as_uint(ct[(r0+8)*20 + k8*8 + t+4]);
            }
            #pragma unroll
            for (int nt=0;nt<4;nt++) {
                int n0 = wn*32 + nt*8 + g;
                bb[nt][0] = __float_as_uint(at[n0*20 + k8*8 + t]);
                bb[nt][1] = __float_as_uint(at[n0*20 + k8*8 + t+4]);
            }
            #pragma unroll
            for (int mt=0;mt<4;mt++)
              #pragma unroll
              for (int nt=0;nt<4;nt++)
                mma8(acc[mt][nt], a[mt], bb[nt]);
        }
        __syncthreads();
    }

    // -------- bias + masks + row softmax over q ------------------------------
    float cm[4][2], qmv[4][2], xqv[4][2];
    #pragma unroll
    for (int mt=0;mt<4;mt++) {
        int r0 = wm*64 + mt*16 + g;
        cm[mt][0] = smf[SCM_F + r0];
        cm[mt][1] = smf[SCM_F + r0 + 8];
    }
    #pragma unroll
    for (int nt=0;nt<4;nt++) {
        int c0 = wn*32 + nt*8 + 2*t;
        qmv[nt][0] = smf[SQM_F + c0];     qmv[nt][1] = smf[SQM_F + c0 + 1];
        xqv[nt][0] = smf[SXQ_F + c0];     xqv[nt][1] = smf[SXQ_F + c0 + 1];
    }
    float rowmax[4][2];
    #pragma unroll
    for (int mt=0;mt<4;mt++) { rowmax[mt][0] = -finf(); rowmax[mt][1] = -finf(); }
    #pragma unroll
    for (int mt=0;mt<4;mt++)
      #pragma unroll
      for (int nt=0;nt<4;nt++)
        #pragma unroll
        for (int r=0;r<4;r++) {
            int h = r>>1, e = r&1;
            float v = (acc[mt][nt][r] + xqv[nt][e]) * cm[mt][h] * qmv[nt][e];
            if (v == finf()) v = -finf();
            acc[mt][nt][r] = v;
            rowmax[mt][h] = fmaxf(rowmax[mt][h], v);
        }
    #pragma unroll
    for (int mt=0;mt<4;mt++)
      #pragma unroll
      for (int h=0;h<2;h++) {
        float m = rowmax[mt][h];
        m = fmaxf(m, __shfl_xor_sync(0xffffffffu, m, 1));
        m = fmaxf(m, __shfl_xor_sync(0xffffffffu, m, 2));
        if (t == 0) smf[SRED_F + (wm*64 + mt*16 + g + 8*h)*4 + wn] = m;
      }
    __syncthreads();
    float mx[4][2];
    #pragma unroll
    for (int mt=0;mt<4;mt++)
      #pragma unroll
      for (int h=0;h<2;h++) {
        int row = wm*64 + mt*16 + g + 8*h;
        float4 mm = *(const float4*)&smf[SRED_F + row*4];
        float m = fmaxf(fmaxf(mm.x, mm.y), fmaxf(mm.z, mm.w));
        mx[mt][h] = m;
        if (wn == 0 && t == 0) g_m[b*CN + cbase + row] = m;
      }
    float rowsum[4][2];
    #pragma unroll
    for (int mt=0;mt<4;mt++) { rowsum[mt][0] = 0.f; rowsum[mt][1] = 0.f; }
    #pragma unroll
    for (int mt=0;mt<4;mt++)
      #pragma unroll
      for (int nt=0;nt<4;nt++)
        #pragma unroll
        for (int r=0;r<4;r++) {
            int h = r>>1;
            float e = expf(acc[mt][nt][r] - mx[mt][h]);
            acc[mt][nt][r] = e;
            rowsum[mt][h] += e;
        }
    __syncthreads();   // all reads of max partials done before overwriting SRED
    #pragma unroll
    for (int mt=0;mt<4;mt++)
      #pragma unroll
      for (int h=0;h<2;h++) {
        float s = rowsum[mt][h];
        s += __shfl_xor_sync(0xffffffffu, s, 1);
        s += __shfl_xor_sync(0xffffffffu, s, 2);
        if (t == 0) smf[SRED_F + (wm*64 + mt*16 + g + 8*h)*4 + wn] = s;
      }
    __syncthreads();
    #pragma unroll
    for (int mt=0;mt<4;mt++)
      #pragma unroll
      for (int h=0;h<2;h++) {
        int row = wm*64 + mt*16 + g + 8*h;
        float4 ss = *(const float4*)&smf[SRED_F + row*4];
        float inv = 1.0f / (ss.x + ss.y + ss.z + ss.w);
        #pragma unroll
        for (int nt=0;nt<4;nt++) {
            float2 pv = make_float2(acc[mt][nt][h*2+0]*inv, acc[mt][nt][h*2+1]*inv);
            *(float2*)&smf[P_F + row*132 + wn*32 + nt*8 + 2*t] = pv;
        }
      }
    __syncthreads();

    // -------- GEMM2: per 64-d chunk O = P @ QT^T ; write parts 1/2/3 ---------
    const float* QTb = g_QT + (size_t)b*DN*QN;
    for (int dc = 0; dc < 12; dc++) {
        const int dbase = dc*64;
        #pragma unroll
        for (int p=0;p<8;p++) {
            int idx = tid + p*256;
            int r = idx>>5, s = idx&31;
            cpa16(sb + (uint32_t)(r*132 + s*4)*4,
                  QTb + (size_t)(dbase + r)*QN + s*4);
        }
        CP_COMMIT(); CP_WAIT0();
        __syncthreads();
        float o2[4][2][4];
        #pragma unroll
        for (int mt=0;mt<4;mt++)
          #pragma unroll
          for (int nt=0;nt<2;nt++)
            #pragma unroll
            for (int r=0;r<4;r++) o2[mt][nt][r]=0.f;
        #pragma unroll 4
        for (int k8=0;k8<16;k8++) {
            uint32_t a[4][4], bb[2][2];
            #pragma unroll
            for (int mt=0;mt<4;mt++) {
                int r0 = wm*64 + mt*16 + g;
                a[mt][0] = __float_as_uint(smf[P_F +  r0   *132 + k8*8 + t]);
                a[mt][1] = __float_as_uint(smf[P_F + (r0+8)*132 + k8*8 + t]);
                a[mt][2] = __float_as_uint(smf[P_F +  r0   *132 + k8*8 + t+4]);
                a[mt][3] = __float_as_uint(smf[P_F + (r0+8)*132 + k8*8 + t+4]);
            }
            #pragma unroll
            for (int nt=0;nt<2;nt++) {
                int n0 = wn*16 + nt*8 + g;
                bb[nt][0] = __float_as_uint(smf[n0*132 + k8*8 + t]);
                bb[nt][1] = __float_as_uint(smf[n0*132 + k8*8 + t+4]);
            }
            #pragma unroll
            for (int mt=0;mt<4;mt++)
              #pragma unroll
              for (int nt=0;nt<2;nt++)
                mma8(o2[mt][nt], a[mt], bb[nt]);
        }
        __syncthreads();      // QT reads done; region A reusable for O stage
        #pragma unroll
        for (int mt=0;mt<4;mt++)
          #pragma unroll
          for (int h=0;h<2;h++) {
            int row = wm*64 + mt*16 + g + 8*h;
            #pragma unroll
            for (int nt=0;nt<2;nt++) {
                float2 ov = make_float2(o2[mt][nt][h*2+0], o2[mt][nt][h*2+1]);
                *(float2*)&smf[row*68 + wn*16 + nt*8 + 2*t] = ov;
            }
          }
        __syncthreads();
        #pragma unroll
        for (int p=0;p<8;p++) {
            int row = p*16 + (tid>>4);
            int c4 = (tid&15)*4;
            float4 ov = *(const float4*)&smf[row*68 + c4];
            size_t orow = (size_t)(b*CN + cbase + row);
            float4 cv = *(const float4*)(ctx + orow*DN + dbase + c4);
            float* op = out + orow*ODN + dbase + c4;
            *(float4*)(op) = cv;
            *(float4*)(op + DN) = ov;
            *(float4*)(op + 2*DN) = make_float4(cv.x*ov.x, cv.y*ov.y, cv.z*ov.z, cv.w*ov.w);
        }
        __syncthreads();
    }
}

// ---------------- kernel 3: q2c weights = softmax over c of g_m --------------
__global__ void softc_kernel() {
    int b = blockIdx.x, t = threadIdx.x;  // 256 threads
    float v[4]; float mx = -finf();
    #pragma unroll
    for (int i=0;i<4;i++) { v[i] = g_m[b*CN + t + i*256]; mx = fmaxf(mx, v[i]); }
    #pragma unroll
    for (int o=16;o;o>>=1) mx = fmaxf(mx, __shfl_xor_sync(0xffffffffu, mx, o));
    __shared__ float smx[8], ssm[8];
    if ((t&31)==0) smx[t>>5]=mx;
    __syncthreads();
    float bm = smx[0];
    #pragma unroll
    for (int i=1;i<8;i++) bm = fmaxf(bm, smx[i]);
    float s = 0.f;
    #pragma unroll
    for (int i=0;i<4;i++) { float e = expf(v[i]-bm); v[i]=e; s+=e; }
    #pragma unroll
    for (int o=16;o;o>>=1) s += __shfl_xor_sync(0xffffffffu, s, o);
    if ((t&31)==0) ssm[t>>5]=s;
    __syncthreads();
    float tot = ssm[0]+ssm[1]+ssm[2]+ssm[3]+ssm[4]+ssm[5]+ssm[6]+ssm[7];
    float inv = 1.0f / tot;
    #pragma unroll
    for (int i=0;i<4;i++) g_w[b*CN + t + i*256] = v[i]*inv;
}

// ---------------- kernel 4: q2c partials over 128-c chunks -------------------
__global__ void q2c_kernel(const float* __restrict__ ctx) {
    int b = blockIdx.y;
    int dbase = blockIdx.x << 7;
    int cz = blockIdx.z;
    int t = threadIdx.x;
    int col = t & 127;
    int half = t >> 7;
    const float* cp = ctx + ((size_t)(b*CN) + cz*128 + half*64)*DN + dbase + col;
    const float* wp = g_w + b*CN + cz*128 + half*64;
    float a0=0.f,a1=0.f,a2=0.f,a3=0.f;
    for (int c=0;c<64;c+=4) {
        a0 += wp[c+0]*cp[(size_t)(c+0)*DN];
        a1 += wp[c+1]*cp[(size_t)(c+1)*DN];
        a2 += wp[c+2]*cp[(size_t)(c+2)*DN];
        a3 += wp[c+3]*cp[(size_t)(c+3)*DN];
    }
    float acc = (a0+a1)+(a2+a3);
    __shared__ float sred[128];
    if (half) sred[col] = acc;
    __syncthreads();
    if (!half) g_qp[((size_t)b*8 + cz)*DN + dbase + col] = acc + sred[col];
}

// ---------------- kernel 4b: reduce 8 partials -------------------------------
__global__ void q2c_reduce() {
    int i = blockIdx.x*256 + threadIdx.x;   // < BN*DN
    int b = i / DN, d = i - b*DN;
    float s = 0.f;
    #pragma unroll
    for (int z=0;z<8;z++) s += g_qp[((size_t)b*8 + z)*DN + d];
    g_q2c[(size_t)b*DN + d] = s;
}

// ---------------- kernel 5: part4 = ctx * q2c --------------------------------
__global__ void part4_kernel(const float* __restrict__ ctx, float* __restrict__ out) {
    int i4 = blockIdx.x*blockDim.x + threadIdx.x;
    int bc = i4 / 192;
    int d4 = i4 - bc*192;
    float4 cv = reinterpret_cast<const float4*>(ctx)[(size_t)bc*192 + d4];
    float4 qv = reinterpret_cast<const float4*>(g_q2c)[(bc>>10)*192 + d4];
    float4 rr = make_float4(cv.x*qv.x, cv.y*qv.y, cv.z*qv.z, cv.w*qv.w);
    reinterpret_cast<float4*>(out)[(size_t)bc*768 + 576 + d4] = rr;
}

// ---------------- launch -----------------------------------------------------
extern "C" void kernel_launch(void* const* d_in, const int* in_sizes, int n_in,
                              void* d_out, int out_size) {
    const float* ctx   = (const float*)d_in[0];
    const int*   cmask = (const int*)d_in[1];
    const float* query = (const float*)d_in[2];
    const int*   qmask = (const int*)d_in[3];
    const float* wq    = (const float*)d_in[4];
    const float* wc    = (const float*)d_in[5];
    const float* wqc   = (const float*)d_in[6];
    float* out = (float*)d_out;

    cudaFuncSetAttribute(main_kernel, cudaFuncAttributeMaxDynamicSharedMemorySize, SMEM_BYTES);

    prep_kernel<<<BN*QN, 192>>>(query, wq, wc, wqc);
    qtrans_kernel<<<dim3(24, 4, BN), dim3(32, 8)>>>(query);
    main_kernel<<<dim3(8, BN), 256, SMEM_BYTES>>>(ctx, cmask, qmask, out);
    softc_kernel<<<BN, 256>>>();
    q2c_kernel<<<dim3(6, BN, 8), 256>>>(ctx);
    q2c_reduce<<<(BN*DN)/256, 256>>>();
    part4_kernel<<<(BN*CN*192)/256, 256>>>(ctx, out);
}